// round 7
// baseline (speedup 1.0000x reference)
#include <cuda_runtime.h>
#include <cuda_fp16.h>
#include <stdint.h>
#include <math.h>

// Problem constants
#define BB 2
#define TT 2048
#define CC 2048
#define HH 16
#define DD 128
#define BH (BB*HH)          // 32

// ---------------- scratch (device globals, no allocation) ----------------
__device__ uint4 g_xh4   [(size_t)BB*TT*CC/8];        // x as half
__device__ uint4 g_wqkvT4[(size_t)3*CC*CC/8];         // W_qkv^T half (6144 x 2048)
__device__ uint4 g_wprojT4[(size_t)CC*CC/8];          // W_proj^T half
__device__ uint4 g_qh4   [(size_t)BB*HH*TT*DD/8];     // q half [B,H,T,D] (post-rope)
__device__ uint4 g_kh4   [(size_t)BB*HH*TT*DD/8];     // k half [B,H,T,D] (post-rope)
__device__ uint4 g_vh4   [(size_t)BB*HH*DD*TT/8];     // v half [B,H,D,T] (transposed)
__device__ uint4 g_ph4   [(size_t)BH*TT*TT/8];        // probs half
__device__ uint4 g_yh4   [(size_t)BB*TT*CC/8];        // y half [B*T, C]
__device__ float g_q[(size_t)BB*HH*TT*DD];            // raw fp32 q (pre-rope)
__device__ float g_k[(size_t)BB*HH*TT*DD];            // raw fp32 k (pre-rope)
__device__ float g_s[(size_t)BH*TT*TT];               // scores fp32

// ---------------- helpers ----------------
__device__ __forceinline__ void cpa16(uint32_t dst, const void* src) {
    asm volatile("cp.async.cg.shared.global [%0], [%1], 16;" :: "r"(dst), "l"(src));
}

__device__ __forceinline__ void ldsm4(uint32_t* r, uint32_t addr) {
    asm volatile("ldmatrix.sync.aligned.m8n8.x4.shared.b16 {%0,%1,%2,%3}, [%4];"
                 : "=r"(r[0]), "=r"(r[1]), "=r"(r[2]), "=r"(r[3]) : "r"(addr));
}

__device__ __forceinline__ void mma_h(float* d, const uint32_t* a, const uint32_t* b) {
    asm volatile(
        "mma.sync.aligned.m16n8k16.row.col.f32.f16.f16.f32 "
        "{%0,%1,%2,%3}, {%4,%5,%6,%7}, {%8,%9}, {%0,%1,%2,%3};"
        : "+f"(d[0]), "+f"(d[1]), "+f"(d[2]), "+f"(d[3])
        : "r"(a[0]), "r"(a[1]), "r"(a[2]), "r"(a[3]),
          "r"(b[0]), "r"(b[1]));
}

// ---------------- fp16 tensor-core GEMM -----------------------------------
// C = alpha * A * B^T.  A: (M x K) half row-major lda; B: (N x K) half row-major.
// CTA tile TM x 128 (TM = 128 or 256), K-tile 32 halves (64B/row).
// Warps = (TM/64)*2, warp tile 64x64. Smem: swizzled 64B rows,
// chunk ^= (row & 3); 3 stages, (TM+128)*64 B/stage, dynamic.
// EPI 0: fp32 C + z*cOut, *alpha
// EPI 1: qkv scatter -> g_q/g_k fp32 [B,H,T,D], v half transposed [B,H,D,T]
// EPI 2: y half at (b*T+row)*C + h*128 + col   (z = b*HH + h)
template<int TM, int EPI>
__global__ __launch_bounds__((TM/64)*64)
void hgemm(const __half* __restrict__ A, const __half* __restrict__ B,
           float* __restrict__ C,
           int K, int lda, int ldb, int ldc,
           long batchA, long batchB, long cOut, float alpha)
{
    constexpr int NT  = (TM / 64) * 64;        // threads: 128 or 256
    constexpr int MW  = TM / 64;               // warps in M
    constexpr uint32_t STG = (uint32_t)(TM + 128) * 64u;

    extern __shared__ __align__(128) char smem[];

    const int tid  = threadIdx.x;
    const int lane = tid & 31;
    const int warp = tid >> 5;
    const int warp_m = (warp % MW) * 64;
    const int warp_n = (warp / MW) * 64;
    const int lg = lane >> 2;
    const int lk = lane & 3;

    const int z = blockIdx.z;
    const __half* Ab = A + (long)z * batchA;
    const __half* Bb = B + (long)z * batchB;
    const int bn = blockIdx.x * 128;
    const int bm = blockIdx.y * TM;

    float acc[4][8][4];
    #pragma unroll
    for (int i = 0; i < 4; i++)
        #pragma unroll
        for (int j = 0; j < 8; j++)
            #pragma unroll
            for (int c = 0; c < 4; c++) acc[i][j][c] = 0.f;

    const uint32_t s0 = (uint32_t)__cvta_generic_to_shared(smem);
    const int nt = K >> 5;

    // ---- cp.async tile loader: A at stage base (TM*64 B), B at +TM*64 ----
    const int strow = tid >> 2;          // 0..NT/4-1
    const int stc   = tid & 3;
    auto ldtile = [&](int t, int st) {
        uint32_t base = s0 + (uint32_t)st * STG;
        int k0 = t << 5;
        #pragma unroll
        for (int p = 0; p < 4; p++) {               // A: TM rows
            int row = strow + p * (NT / 4);
            uint32_t sw = (uint32_t)(row * 64 + ((stc ^ (row & 3)) << 4));
            cpa16(base + sw, Ab + (long)(bm + row) * lda + k0 + stc * 8);
        }
        #pragma unroll
        for (int p = 0; p < 512 / NT; p++) {        // B: 128 rows
            int row = strow + p * (NT / 4);
            uint32_t sw = (uint32_t)(row * 64 + ((stc ^ (row & 3)) << 4));
            cpa16(base + (uint32_t)TM * 64u + sw,
                  Bb + (long)(bn + row) * ldb + k0 + stc * 8);
        }
        asm volatile("cp.async.commit_group;" ::: "memory");
    };

    // ---- ldmatrix per-lane rows ----
    const int rowA  = warp_m + (lane & 15);
    const int chA   = lane >> 4;
    const int rowB  = warp_n + (lane & 7) + ((lane >> 4) << 3);
    const int chB   = (lane >> 3) & 1;

    ldtile(0, 0);
    if (nt > 1) ldtile(1, 1);

    for (int it = 0; it < nt; it++) {
        if (it + 1 < nt) asm volatile("cp.async.wait_group 1;" ::: "memory");
        else             asm volatile("cp.async.wait_group 0;" ::: "memory");
        __syncthreads();   // orders prior-iter LDSMs before stage reuse below

        if (it + 2 < nt) ldtile(it + 2, (it + 2) % 3);

        uint32_t abase = s0 + (uint32_t)(it % 3) * STG;
        uint32_t bbase = abase + (uint32_t)TM * 64u;

        #pragma unroll
        for (int ks = 0; ks < 2; ks++) {
            int kc = ks * 2;
            uint32_t af[4][4];
            #pragma unroll
            for (int i = 0; i < 4; i++) {
                int r = rowA + i * 16;
                ldsm4(af[i], abase + r * 64 + (((kc + chA) ^ (r & 3)) << 4));
            }
            uint32_t bf[8][2];
            #pragma unroll
            for (int j4 = 0; j4 < 4; j4++) {
                int r = rowB + j4 * 16;
                uint32_t t4[4];
                ldsm4(t4, bbase + r * 64 + (((kc + chB) ^ (r & 3)) << 4));
                bf[j4 * 2][0]     = t4[0];
                bf[j4 * 2][1]     = t4[1];
                bf[j4 * 2 + 1][0] = t4[2];
                bf[j4 * 2 + 1][1] = t4[3];
            }
            #pragma unroll
            for (int i = 0; i < 4; i++)
                #pragma unroll
                for (int j = 0; j < 8; j++)
                    mma_h(acc[i][j], af[i], bf[j]);
        }
    }

    // ---- epilogue ----
    if (EPI == 0) {
        float* Cb = C + (long)z * cOut;
        #pragma unroll
        for (int i = 0; i < 4; i++) {
            long r0 = bm + warp_m + i * 16 + lg;
            #pragma unroll
            for (int j = 0; j < 8; j++) {
                int col = bn + warp_n + j * 8 + lk * 2;
                *(float2*)&Cb[r0 * ldc + col] =
                    make_float2(alpha * acc[i][j][0], alpha * acc[i][j][1]);
                *(float2*)&Cb[(r0 + 8) * ldc + col] =
                    make_float2(alpha * acc[i][j][2], alpha * acc[i][j][3]);
            }
        }
    } else if (EPI == 1) {
        int sel = bn >> 11;
        int h   = (bn & 2047) >> 7;
        #pragma unroll
        for (int i = 0; i < 4; i++) {
            int rowm = bm + warp_m + i * 16 + lg;
            int b = rowm >> 11;
            int t = rowm & 2047;
            if (sel < 2) {
                float* dst = sel ? g_k : g_q;
                long base = ((long)(b * HH + h) * TT + t) * DD;
                #pragma unroll
                for (int j = 0; j < 8; j++) {
                    int d = warp_n + j * 8 + lk * 2;
                    *(float2*)&dst[base + d] =
                        make_float2(acc[i][j][0], acc[i][j][1]);
                    *(float2*)&dst[base + 8 * DD + d] =
                        make_float2(acc[i][j][2], acc[i][j][3]);
                }
            } else {
                __half* vh = (__half*)g_vh4;
                long vb = (long)(b * HH + h) * DD * TT;
                #pragma unroll
                for (int j = 0; j < 8; j++) {
                    int d = warp_n + j * 8 + lk * 2;
                    vh[vb + (long)d       * TT + t]     = __float2half_rn(acc[i][j][0]);
                    vh[vb + (long)(d + 1) * TT + t]     = __float2half_rn(acc[i][j][1]);
                    vh[vb + (long)d       * TT + t + 8] = __float2half_rn(acc[i][j][2]);
                    vh[vb + (long)(d + 1) * TT + t + 8] = __float2half_rn(acc[i][j][3]);
                }
            }
        }
    } else { // EPI == 2
        __half* yh = (__half*)g_yh4;
        int h = z % HH, b = z / HH;
        #pragma unroll
        for (int i = 0; i < 4; i++) {
            int rowm = bm + warp_m + i * 16 + lg;
            long base = ((long)(b * TT + rowm)) * CC + h * DD;
            #pragma unroll
            for (int j = 0; j < 8; j++) {
                int col = warp_n + j * 8 + lk * 2;
                *(__half2*)&yh[base + col] =
                    __floats2half2_rn(acc[i][j][0], acc[i][j][1]);
                *(__half2*)&yh[base + 8 * CC + col] =
                    __floats2half2_rn(acc[i][j][2], acc[i][j][3]);
            }
        }
    }
}

// ---------------- prepass: fp32 -> fp16 ----------------
__global__ __launch_bounds__(256)
void f2h_kernel(const float4* __restrict__ src, uint2* __restrict__ dst, int n4)
{
    int i = blockIdx.x * blockDim.x + threadIdx.x;
    if (i >= n4) return;
    float4 v = src[i];
    uint2 o;
    __half2 lo = __floats2half2_rn(v.x, v.y);
    __half2 hi = __floats2half2_rn(v.z, v.w);
    o.x = *(uint32_t*)&lo;
    o.y = *(uint32_t*)&hi;
    dst[i] = o;
}

__global__ __launch_bounds__(256)
void transpose_h_kernel(const float* __restrict__ src, __half* __restrict__ dst,
                        int R, int C)
{
    __shared__ float t[32][33];
    int c0 = blockIdx.x * 32, r0 = blockIdx.y * 32;
    int tx = threadIdx.x, ty = threadIdx.y;   // (32, 8)
    #pragma unroll
    for (int i = 0; i < 32; i += 8)
        t[ty + i][tx] = src[(long)(r0 + ty + i) * C + c0 + tx];
    __syncthreads();
    #pragma unroll
    for (int i = 0; i < 32; i += 8)
        dst[(long)(c0 + ty + i) * R + r0 + tx] = __float2half_rn(t[tx][ty + i]);
}

// ---------------- RoPE: fp32 q/k -> rotated fp16 qh/kh ----------------
__global__ __launch_bounds__(256)
void rope_kernel(const float* __restrict__ cosb, const float* __restrict__ sinb)
{
    long idx = (long)blockIdx.x * blockDim.x + threadIdx.x;
    const long total = (long)BB * HH * TT * 64;
    if (idx >= total) return;
    int d = idx & 63;
    long r = idx >> 6;
    int t = (int)(r % TT);
    long base = r * DD + d;
    float c = cosb[t * DD + d];
    float s = sinb[t * DD + d];
    __half* qh = (__half*)g_qh4;
    __half* kh = (__half*)g_kh4;
    float q0 = g_q[base], q1 = g_q[base + 64];
    qh[base]      = __float2half_rn(q0 * c - q1 * s);
    qh[base + 64] = __float2half_rn(q1 * c + q0 * s);
    float k0 = g_k[base], k1 = g_k[base + 64];
    kh[base]      = __float2half_rn(k0 * c - k1 * s);
    kh[base + 64] = __float2half_rn(k1 * c + k0 * s);
}

// ---------------- row softmax: fp32 scores -> fp16 probs ----------------
__global__ __launch_bounds__(256)
void softmax_kernel()
{
    long row = blockIdx.x;
    const float* p = g_s + row * (long)TT;
    __half* ph = (__half*)g_ph4 + row * (long)TT;
    int tid = threadIdx.x;
    float v[8];
    float mx = -1e30f;
    #pragma unroll
    for (int i = 0; i < 8; i++) {
        v[i] = p[tid + i * 256];
        mx = fmaxf(mx, v[i]);
    }
    __shared__ float sm[8];
    #pragma unroll
    for (int o = 16; o; o >>= 1) mx = fmaxf(mx, __shfl_xor_sync(0xffffffffu, mx, o));
    if ((tid & 31) == 0) sm[tid >> 5] = mx;
    __syncthreads();
    float rowmax = sm[0];
    #pragma unroll
    for (int w = 1; w < 8; w++) rowmax = fmaxf(rowmax, sm[w]);
    __syncthreads();

    float sum = 0.f;
    #pragma unroll
    for (int i = 0; i < 8; i++) {
        v[i] = expf(v[i] - rowmax);
        sum += v[i];
    }
    #pragma unroll
    for (int o = 16; o; o >>= 1) sum += __shfl_xor_sync(0xffffffffu, sum, o);
    if ((tid & 31) == 0) sm[tid >> 5] = sum;
    __syncthreads();
    float rowsum = 0.f;
    #pragma unroll
    for (int w = 0; w < 8; w++) rowsum += sm[w];
    float inv = 1.f / rowsum;
    #pragma unroll
    for (int i = 0; i < 8; i++) ph[tid + i * 256] = __float2half_rn(v[i] * inv);
}

// ---------------- launch ----------------
extern "C" void kernel_launch(void* const* d_in, const int* in_sizes, int n_in,
                              void* d_out, int out_size)
{
    const float* x     = (const float*)d_in[0];
    const float* cosb  = (const float*)d_in[1];
    const float* sinb  = (const float*)d_in[2];
    const float* Wqkv  = (const float*)d_in[3];
    const float* Wproj = (const float*)d_in[4];
    float* out = (float*)d_out;

    void *xh, *wqkvT, *wprojT, *qh, *kh, *vh, *ph, *yh;
    float *s;
    cudaGetSymbolAddress(&xh,     g_xh4);
    cudaGetSymbolAddress(&wqkvT,  g_wqkvT4);
    cudaGetSymbolAddress(&wprojT, g_wprojT4);
    cudaGetSymbolAddress(&qh, g_qh4);
    cudaGetSymbolAddress(&kh, g_kh4);
    cudaGetSymbolAddress(&vh, g_vh4);
    cudaGetSymbolAddress(&ph, g_ph4);
    cudaGetSymbolAddress(&yh, g_yh4);
    cudaGetSymbolAddress((void**)&s, g_s);

    const int SM256 = 3 * (256 + 128) * 64;   // 73728
    const int SM128 = 3 * (128 + 128) * 64;   // 49152
    cudaFuncSetAttribute(hgemm<256,0>, cudaFuncAttributeMaxDynamicSharedMemorySize, SM256);
    cudaFuncSetAttribute(hgemm<256,1>, cudaFuncAttributeMaxDynamicSharedMemorySize, SM256);
    cudaFuncSetAttribute(hgemm<128,2>, cudaFuncAttributeMaxDynamicSharedMemorySize, SM128);

    const float scale = 0.08838834764831845f;  // 1/sqrt(128)

    // 0) prepass: x -> half; W_qkv^T, W_proj^T -> half
    {
        int n4 = (BB * TT * CC) / 4;
        f2h_kernel<<<(n4 + 255) / 256, 256>>>((const float4*)x, (uint2*)xh, n4);
        transpose_h_kernel<<<dim3(3 * CC / 32, CC / 32), dim3(32, 8)>>>(Wqkv,  (__half*)wqkvT,  CC, 3 * CC);
        transpose_h_kernel<<<dim3(CC / 32,     CC / 32), dim3(32, 8)>>>(Wproj, (__half*)wprojT, CC, CC);
    }

    // 1) qkv = x @ W_qkv  -> q,k fp32 [B,H,T,D]; v half [B,H,D,T]
    hgemm<256,1><<<dim3(48, 16, 1), 256, SM256>>>(
        (const __half*)xh, (const __half*)wqkvT, nullptr,
        2048, 2048, 2048, 0,
        0L, 0L, 0L, 1.0f);

    // 2) RoPE -> qh, kh (half)
    rope_kernel<<<16384, 256>>>(cosb, sinb);

    // 3) scores = scale * Q @ K^T -> g_s fp32 (batched over B*H)
    hgemm<256,0><<<dim3(16, 8, BH), 256, SM256>>>(
        (const __half*)qh, (const __half*)kh, s,
        128, 128, 128, 2048,
        (long)TT * DD, (long)TT * DD, (long)TT * TT, scale);

    // 4) softmax -> probs half
    softmax_kernel<<<BH * TT, 256>>>();

    // 5) y = P @ V -> yh half [B*T, C]
    hgemm<128,2><<<dim3(1, 16, BH), 128, SM128>>>(
        (const __half*)ph, (const __half*)vh, nullptr,
        2048, 2048, 2048, 0,
        (long)TT * TT, (long)DD * TT, 0L, 1.0f);

    // 6) out = y @ W_proj -> fp32
    hgemm<256,0><<<dim3(16, 16, 1), 256, SM256>>>(
        (const __half*)yh, (const __half*)wprojT, out,
        2048, 2048, 2048, 2048,
        0L, 0L, 0L, 1.0f);
}

// round 8
// speedup vs baseline: 1.3924x; 1.3924x over previous
#include <cuda_runtime.h>
#include <cuda_fp16.h>
#include <stdint.h>
#include <math.h>

// Problem constants
#define BB 2
#define TT 2048
#define CC 2048
#define HH 16
#define DD 128
#define BH (BB*HH)          // 32

// ---------------- scratch (device globals, no allocation) ----------------
__device__ uint4 g_xh4   [(size_t)BB*TT*CC/8];        // x as half
__device__ uint4 g_wqkvT4[(size_t)3*CC*CC/8];         // W_qkv^T half (6144 x 2048)
__device__ uint4 g_wprojT4[(size_t)CC*CC/8];          // W_proj^T half
__device__ uint4 g_qh4   [(size_t)BB*HH*TT*DD/8];     // q half [B,H,T,D] (post-rope)
__device__ uint4 g_kh4   [(size_t)BB*HH*TT*DD/8];     // k half [B,H,T,D] (post-rope)
__device__ uint4 g_vh4   [(size_t)BB*HH*DD*TT/8];     // v half [B,H,D,T] (transposed)
__device__ uint4 g_ph4   [(size_t)BH*TT*TT/8];        // probs half
__device__ uint4 g_yh4   [(size_t)BB*TT*CC/8];        // y half [B*T, C]
__device__ float g_q[(size_t)BB*HH*TT*DD];            // raw fp32 q (pre-rope)
__device__ float g_k[(size_t)BB*HH*TT*DD];            // raw fp32 k (pre-rope)
__device__ float g_s[(size_t)BH*TT*TT];               // scores fp32

// ---------------- helpers ----------------
__device__ __forceinline__ void cpa16(uint32_t dst, const void* src) {
    asm volatile("cp.async.cg.shared.global [%0], [%1], 16;" :: "r"(dst), "l"(src));
}

__device__ __forceinline__ void ldsm4(uint32_t* r, uint32_t addr) {
    asm volatile("ldmatrix.sync.aligned.m8n8.x4.shared.b16 {%0,%1,%2,%3}, [%4];"
                 : "=r"(r[0]), "=r"(r[1]), "=r"(r[2]), "=r"(r[3]) : "r"(addr));
}

__device__ __forceinline__ void mma_h(float* d, const uint32_t* a, const uint32_t* b) {
    asm volatile(
        "mma.sync.aligned.m16n8k16.row.col.f32.f16.f16.f32 "
        "{%0,%1,%2,%3}, {%4,%5,%6,%7}, {%8,%9}, {%0,%1,%2,%3};"
        : "+f"(d[0]), "+f"(d[1]), "+f"(d[2]), "+f"(d[3])
        : "r"(a[0]), "r"(a[1]), "r"(a[2]), "r"(a[3]),
          "r"(b[0]), "r"(b[1]));
}

// ---------------- fp16 tensor-core GEMM -----------------------------------
// C = alpha * A * B^T.  A: (M x K) half row-major lda; B: (N x K) half row-major.
// CTA tile 128x128, K-tile 64 halves (128B rows), 128 threads, 4 warps (2Mx2N),
// warp tile 64x64. Smem: 128B rows, 16B chunk swizzle c ^= (row & 7);
// 3 stages x 32KB = 96KB dynamic. Register fragment double-buffering over the
// 4 k16-steps per tile.
// EPI 0: fp32 C + z*cOut, *alpha
// EPI 1: qkv scatter -> g_q/g_k fp32 [B,H,T,D], v half transposed [B,H,D,T]
// EPI 2: y half at (b*T+row)*C + h*128 + col   (z = b*HH + h)
#define STG_BYTES 32768u
template<int EPI>
__global__ __launch_bounds__(128)
void hgemm(const __half* __restrict__ A, const __half* __restrict__ B,
           float* __restrict__ C,
           int K, int lda, int ldb, int ldc,
           long batchA, long batchB, long cOut, float alpha)
{
    extern __shared__ __align__(128) char smem[];

    const int tid  = threadIdx.x;
    const int lane = tid & 31;
    const int warp = tid >> 5;                // 0..3
    const int warp_m = (warp & 1) * 64;       // 0,64
    const int warp_n = (warp >> 1) * 64;      // 0,64
    const int lg = lane >> 2;
    const int lk = lane & 3;

    const int z = blockIdx.z;
    const __half* Ab = A + (long)z * batchA;
    const __half* Bb = B + (long)z * batchB;
    const int bn = blockIdx.x * 128;
    const int bm = blockIdx.y * 128;

    float acc[4][8][4];
    #pragma unroll
    for (int i = 0; i < 4; i++)
        #pragma unroll
        for (int j = 0; j < 8; j++)
            #pragma unroll
            for (int c = 0; c < 4; c++) acc[i][j][c] = 0.f;

    const uint32_t s0 = (uint32_t)__cvta_generic_to_shared(smem);
    const int nt = K >> 6;

    // ---- cp.async tile loader: A at stage base (16KB), B at +16KB ----
    const int r8 = tid >> 3;         // 0..15
    const int cc = tid & 7;          // chunk 0..7
    auto ldtile = [&](int t, int st) {
        uint32_t base = s0 + (uint32_t)st * STG_BYTES;
        int k0 = t << 6;
        #pragma unroll
        for (int p = 0; p < 8; p++) {
            int row = r8 + p * 16;
            uint32_t sc = (uint32_t)(cc ^ (row & 7));
            cpa16(base + row * 128 + sc * 16,
                  Ab + (long)(bm + row) * lda + k0 + cc * 8);
            cpa16(base + 16384u + row * 128 + sc * 16,
                  Bb + (long)(bn + row) * ldb + k0 + cc * 8);
        }
        asm volatile("cp.async.commit_group;" ::: "memory");
    };

    // ---- ldmatrix per-lane rows ----
    const int rowA  = warp_m + (lane & 15);
    const int chA   = lane >> 4;
    const int rowB  = warp_n + (lane & 7) + ((lane >> 4) << 3);
    const int chB   = (lane >> 3) & 1;

    uint32_t af[2][4][4];
    uint32_t bf[2][8][2];
    auto ldfrag = [&](int ks, int bi, uint32_t abase, uint32_t bbase) {
        int kc = ks << 1;
        #pragma unroll
        for (int i = 0; i < 4; i++) {
            int r = rowA + i * 16;
            ldsm4(af[bi][i], abase + r * 128 + (((kc + chA) ^ (r & 7)) << 4));
        }
        #pragma unroll
        for (int j4 = 0; j4 < 4; j4++) {
            int r = rowB + j4 * 16;
            uint32_t t4[4];
            ldsm4(t4, bbase + r * 128 + (((kc + chB) ^ (r & 7)) << 4));
            bf[bi][j4 * 2][0]     = t4[0];
            bf[bi][j4 * 2][1]     = t4[1];
            bf[bi][j4 * 2 + 1][0] = t4[2];
            bf[bi][j4 * 2 + 1][1] = t4[3];
        }
    };

    ldtile(0, 0);
    if (nt > 1) ldtile(1, 1);

    for (int it = 0; it < nt; it++) {
        if (it + 1 < nt) asm volatile("cp.async.wait_group 1;" ::: "memory");
        else             asm volatile("cp.async.wait_group 0;" ::: "memory");
        __syncthreads();   // orders prior-iter LDSMs before stage reuse below

        uint32_t abase = s0 + (uint32_t)(it % 3) * STG_BYTES;
        uint32_t bbase = abase + 16384u;

        ldfrag(0, 0, abase, bbase);          // first frags ASAP after barrier
        if (it + 2 < nt) ldtile(it + 2, (it + 2) % 3);

        #pragma unroll
        for (int ks = 0; ks < 4; ks++) {
            if (ks < 3) ldfrag(ks + 1, (ks + 1) & 1, abase, bbase);
            int bi = ks & 1;
            #pragma unroll
            for (int i = 0; i < 4; i++)
                #pragma unroll
                for (int j = 0; j < 8; j++)
                    mma_h(acc[i][j], af[bi][i], bf[bi][j]);
        }
    }

    // ---- epilogue ----
    if (EPI == 0) {
        float* Cb = C + (long)z * cOut;
        #pragma unroll
        for (int i = 0; i < 4; i++) {
            long r0 = bm + warp_m + i * 16 + lg;
            #pragma unroll
            for (int j = 0; j < 8; j++) {
                int col = bn + warp_n + j * 8 + lk * 2;
                *(float2*)&Cb[r0 * ldc + col] =
                    make_float2(alpha * acc[i][j][0], alpha * acc[i][j][1]);
                *(float2*)&Cb[(r0 + 8) * ldc + col] =
                    make_float2(alpha * acc[i][j][2], alpha * acc[i][j][3]);
            }
        }
    } else if (EPI == 1) {
        int sel = bn >> 11;
        int h   = (bn & 2047) >> 7;
        #pragma unroll
        for (int i = 0; i < 4; i++) {
            int rowm = bm + warp_m + i * 16 + lg;
            int b = rowm >> 11;
            int t = rowm & 2047;
            if (sel < 2) {
                float* dst = sel ? g_k : g_q;
                long base = ((long)(b * HH + h) * TT + t) * DD;
                #pragma unroll
                for (int j = 0; j < 8; j++) {
                    int d = warp_n + j * 8 + lk * 2;
                    *(float2*)&dst[base + d] =
                        make_float2(acc[i][j][0], acc[i][j][1]);
                    *(float2*)&dst[base + 8 * DD + d] =
                        make_float2(acc[i][j][2], acc[i][j][3]);
                }
            } else {
                __half* vh = (__half*)g_vh4;
                long vb = (long)(b * HH + h) * DD * TT;
                #pragma unroll
                for (int j = 0; j < 8; j++) {
                    int d = warp_n + j * 8 + lk * 2;
                    vh[vb + (long)d       * TT + t]     = __float2half_rn(acc[i][j][0]);
                    vh[vb + (long)(d + 1) * TT + t]     = __float2half_rn(acc[i][j][1]);
                    vh[vb + (long)d       * TT + t + 8] = __float2half_rn(acc[i][j][2]);
                    vh[vb + (long)(d + 1) * TT + t + 8] = __float2half_rn(acc[i][j][3]);
                }
            }
        }
    } else { // EPI == 2
        __half* yh = (__half*)g_yh4;
        int h = z % HH, b = z / HH;
        #pragma unroll
        for (int i = 0; i < 4; i++) {
            int rowm = bm + warp_m + i * 16 + lg;
            long base = ((long)(b * TT + rowm)) * CC + h * DD;
            #pragma unroll
            for (int j = 0; j < 8; j++) {
                int col = warp_n + j * 8 + lk * 2;
                *(__half2*)&yh[base + col] =
                    __floats2half2_rn(acc[i][j][0], acc[i][j][1]);
                *(__half2*)&yh[base + 8 * CC + col] =
                    __floats2half2_rn(acc[i][j][2], acc[i][j][3]);
            }
        }
    }
}

// ---------------- prepass: fp32 -> fp16 ----------------
__global__ __launch_bounds__(256)
void f2h_kernel(const float4* __restrict__ src, uint2* __restrict__ dst, int n4)
{
    int i = blockIdx.x * blockDim.x + threadIdx.x;
    if (i >= n4) return;
    float4 v = src[i];
    uint2 o;
    __half2 lo = __floats2half2_rn(v.x, v.y);
    __half2 hi = __floats2half2_rn(v.z, v.w);
    o.x = *(uint32_t*)&lo;
    o.y = *(uint32_t*)&hi;
    dst[i] = o;
}

__global__ __launch_bounds__(256)
void transpose_h_kernel(const float* __restrict__ src, __half* __restrict__ dst,
                        int R, int C)
{
    __shared__ float t[32][33];
    int c0 = blockIdx.x * 32, r0 = blockIdx.y * 32;
    int tx = threadIdx.x, ty = threadIdx.y;   // (32, 8)
    #pragma unroll
    for (int i = 0; i < 32; i += 8)
        t[ty + i][tx] = src[(long)(r0 + ty + i) * C + c0 + tx];
    __syncthreads();
    #pragma unroll
    for (int i = 0; i < 32; i += 8)
        dst[(long)(c0 + ty + i) * R + r0 + tx] = __float2half_rn(t[tx][ty + i]);
}

// ---------------- RoPE: fp32 q/k -> rotated fp16 qh/kh ----------------
__global__ __launch_bounds__(256)
void rope_kernel(const float* __restrict__ cosb, const float* __restrict__ sinb)
{
    long idx = (long)blockIdx.x * blockDim.x + threadIdx.x;
    const long total = (long)BB * HH * TT * 64;
    if (idx >= total) return;
    int d = idx & 63;
    long r = idx >> 6;
    int t = (int)(r % TT);
    long base = r * DD + d;
    float c = cosb[t * DD + d];
    float s = sinb[t * DD + d];
    __half* qh = (__half*)g_qh4;
    __half* kh = (__half*)g_kh4;
    float q0 = g_q[base], q1 = g_q[base + 64];
    qh[base]      = __float2half_rn(q0 * c - q1 * s);
    qh[base + 64] = __float2half_rn(q1 * c + q0 * s);
    float k0 = g_k[base], k1 = g_k[base + 64];
    kh[base]      = __float2half_rn(k0 * c - k1 * s);
    kh[base + 64] = __float2half_rn(k1 * c + k0 * s);
}

// ---------------- row softmax: fp32 scores -> fp16 probs ----------------
__global__ __launch_bounds__(256)
void softmax_kernel()
{
    long row = blockIdx.x;
    const float* p = g_s + row * (long)TT;
    __half* ph = (__half*)g_ph4 + row * (long)TT;
    int tid = threadIdx.x;
    float v[8];
    float mx = -1e30f;
    #pragma unroll
    for (int i = 0; i < 8; i++) {
        v[i] = p[tid + i * 256];
        mx = fmaxf(mx, v[i]);
    }
    __shared__ float sm[8];
    #pragma unroll
    for (int o = 16; o; o >>= 1) mx = fmaxf(mx, __shfl_xor_sync(0xffffffffu, mx, o));
    if ((tid & 31) == 0) sm[tid >> 5] = mx;
    __syncthreads();
    float rowmax = sm[0];
    #pragma unroll
    for (int w = 1; w < 8; w++) rowmax = fmaxf(rowmax, sm[w]);
    __syncthreads();

    float sum = 0.f;
    #pragma unroll
    for (int i = 0; i < 8; i++) {
        v[i] = expf(v[i] - rowmax);
        sum += v[i];
    }
    #pragma unroll
    for (int o = 16; o; o >>= 1) sum += __shfl_xor_sync(0xffffffffu, sum, o);
    if ((tid & 31) == 0) sm[tid >> 5] = sum;
    __syncthreads();
    float rowsum = 0.f;
    #pragma unroll
    for (int w = 0; w < 8; w++) rowsum += sm[w];
    float inv = 1.f / rowsum;
    #pragma unroll
    for (int i = 0; i < 8; i++) ph[tid + i * 256] = __float2half_rn(v[i] * inv);
}

// ---------------- launch ----------------
extern "C" void kernel_launch(void* const* d_in, const int* in_sizes, int n_in,
                              void* d_out, int out_size)
{
    const float* x     = (const float*)d_in[0];
    const float* cosb  = (const float*)d_in[1];
    const float* sinb  = (const float*)d_in[2];
    const float* Wqkv  = (const float*)d_in[3];
    const float* Wproj = (const float*)d_in[4];
    float* out = (float*)d_out;

    void *xh, *wqkvT, *wprojT, *qh, *kh, *vh, *ph, *yh;
    float *s;
    cudaGetSymbolAddress(&xh,     g_xh4);
    cudaGetSymbolAddress(&wqkvT,  g_wqkvT4);
    cudaGetSymbolAddress(&wprojT, g_wprojT4);
    cudaGetSymbolAddress(&qh, g_qh4);
    cudaGetSymbolAddress(&kh, g_kh4);
    cudaGetSymbolAddress(&vh, g_vh4);
    cudaGetSymbolAddress(&ph, g_ph4);
    cudaGetSymbolAddress(&yh, g_yh4);
    cudaGetSymbolAddress((void**)&s, g_s);

    const int SMEM = 3 * 32768;   // 96KB dynamic
    cudaFuncSetAttribute(hgemm<0>, cudaFuncAttributeMaxDynamicSharedMemorySize, SMEM);
    cudaFuncSetAttribute(hgemm<1>, cudaFuncAttributeMaxDynamicSharedMemorySize, SMEM);
    cudaFuncSetAttribute(hgemm<2>, cudaFuncAttributeMaxDynamicSharedMemorySize, SMEM);

    const float scale = 0.08838834764831845f;  // 1/sqrt(128)

    // 0) prepass: x -> half; W_qkv^T, W_proj^T -> half
    {
        int n4 = (BB * TT * CC) / 4;
        f2h_kernel<<<(n4 + 255) / 256, 256>>>((const float4*)x, (uint2*)xh, n4);
        transpose_h_kernel<<<dim3(3 * CC / 32, CC / 32), dim3(32, 8)>>>(Wqkv,  (__half*)wqkvT,  CC, 3 * CC);
        transpose_h_kernel<<<dim3(CC / 32,     CC / 32), dim3(32, 8)>>>(Wproj, (__half*)wprojT, CC, CC);
    }

    // 1) qkv = x @ W_qkv  -> q,k fp32 [B,H,T,D]; v half [B,H,D,T]
    hgemm<1><<<dim3(48, 32, 1), 128, SMEM>>>(
        (const __half*)xh, (const __half*)wqkvT, nullptr,
        2048, 2048, 2048, 0,
        0L, 0L, 0L, 1.0f);

    // 2) RoPE -> qh, kh (half)
    rope_kernel<<<16384, 256>>>(cosb, sinb);

    // 3) scores = scale * Q @ K^T -> g_s fp32 (batched over B*H)
    hgemm<0><<<dim3(16, 16, BH), 128, SMEM>>>(
        (const __half*)qh, (const __half*)kh, s,
        128, 128, 128, 2048,
        (long)TT * DD, (long)TT * DD, (long)TT * TT, scale);

    // 4) softmax -> probs half
    softmax_kernel<<<BH * TT, 256>>>();

    // 5) y = P @ V -> yh half [B*T, C]
    hgemm<2><<<dim3(1, 16, BH), 128, SMEM>>>(
        (const __half*)ph, (const __half*)vh, nullptr,
        2048, 2048, 2048, 0,
        (long)TT * TT, (long)DD * TT, 0L, 1.0f);

    // 6) out = y @ W_proj -> fp32
    hgemm<0><<<dim3(16, 32, 1), 128, SMEM>>>(
        (const __half*)yh, (const __half*)wprojT, out,
        2048, 2048, 2048, 2048,
        0L, 0L, 0L, 1.0f);
}

// round 9
// speedup vs baseline: 1.3937x; 1.0010x over previous
#include <cuda_runtime.h>
#include <cuda_fp16.h>
#include <stdint.h>
#include <math.h>

// Problem constants
#define BB 2
#define TT 2048
#define CC 2048
#define HH 16
#define DD 128
#define BH (BB*HH)          // 32

// ---------------- scratch (device globals, no allocation) ----------------
__device__ uint4 g_xh4   [(size_t)BB*TT*CC/8];        // x as half
__device__ uint4 g_wqkvT4[(size_t)3*CC*CC/8];         // W_qkv^T half (6144 x 2048)
__device__ uint4 g_wprojT4[(size_t)CC*CC/8];          // W_proj^T half
__device__ uint4 g_qh4   [(size_t)BB*HH*TT*DD/8];     // q half [B,H,T,D] (post-rope)
__device__ uint4 g_kh4   [(size_t)BB*HH*TT*DD/8];     // k half [B,H,T,D] (post-rope)
__device__ uint4 g_vh4   [(size_t)BB*HH*DD*TT/8];     // v half [B,H,D,T] (transposed)
__device__ uint4 g_ph4   [(size_t)BH*TT*TT/8];        // probs half
__device__ uint4 g_yh4   [(size_t)BB*TT*CC/8];        // y half [B*T, C]
__device__ float g_q[(size_t)BB*HH*TT*DD];            // raw fp32 q (pre-rope)
__device__ float g_k[(size_t)BB*HH*TT*DD];            // raw fp32 k (pre-rope)
__device__ float g_s[(size_t)BH*TT*TT];               // scores fp32

// ---------------- helpers ----------------
__device__ __forceinline__ void cpa16(uint32_t dst, const void* src) {
    asm volatile("cp.async.cg.shared.global [%0], [%1], 16;" :: "r"(dst), "l"(src));
}

__device__ __forceinline__ void ldsm4(uint32_t* r, uint32_t addr) {
    asm volatile("ldmatrix.sync.aligned.m8n8.x4.shared.b16 {%0,%1,%2,%3}, [%4];"
                 : "=r"(r[0]), "=r"(r[1]), "=r"(r[2]), "=r"(r[3]) : "r"(addr));
}

__device__ __forceinline__ void mma_h(float* d, const uint32_t* a, const uint32_t* b) {
    asm volatile(
        "mma.sync.aligned.m16n8k16.row.col.f32.f16.f16.f32 "
        "{%0,%1,%2,%3}, {%4,%5,%6,%7}, {%8,%9}, {%0,%1,%2,%3};"
        : "+f"(d[0]), "+f"(d[1]), "+f"(d[2]), "+f"(d[3])
        : "r"(a[0]), "r"(a[1]), "r"(a[2]), "r"(a[3]),
          "r"(b[0]), "r"(b[1]));
}

// ---------------- fp16 tensor-core GEMM -----------------------------------
// C = alpha * A * B^T.  A: (M x K) half row-major lda; B: (N x K) half row-major.
// CTA tile 128x128, K-tile 64 halves (128B rows), 128 threads, 4 warps (2Mx2N),
// warp tile 64x64. Smem: 128B rows, 16B chunk swizzle c ^= (row & 7);
// 3 stages x 32KB = 96KB dynamic. Register fragment double-buffering over the
// 4 k16-steps per tile.
// EPI 0: fp32 C + z*cOut, *alpha
// EPI 1: qkv scatter -> g_q/g_k fp32 [B,H,T,D], v half transposed [B,H,D,T]
// EPI 2: y half at (b*T+row)*C + h*128 + col   (z = b*HH + h)
#define STG_BYTES 32768u
template<int EPI>
__global__ __launch_bounds__(128)
void hgemm(const __half* __restrict__ A, const __half* __restrict__ B,
           float* __restrict__ C,
           int K, int lda, int ldb, int ldc,
           long batchA, long batchB, long cOut, float alpha)
{
    extern __shared__ __align__(128) char smem[];

    const int tid  = threadIdx.x;
    const int lane = tid & 31;
    const int warp = tid >> 5;                // 0..3
    const int warp_m = (warp & 1) * 64;       // 0,64
    const int warp_n = (warp >> 1) * 64;      // 0,64
    const int lg = lane >> 2;
    const int lk = lane & 3;

    const int z = blockIdx.z;
    const __half* Ab = A + (long)z * batchA;
    const __half* Bb = B + (long)z * batchB;
    const int bn = blockIdx.x * 128;
    const int bm = blockIdx.y * 128;

    float acc[4][8][4];
    #pragma unroll
    for (int i = 0; i < 4; i++)
        #pragma unroll
        for (int j = 0; j < 8; j++)
            #pragma unroll
            for (int c = 0; c < 4; c++) acc[i][j][c] = 0.f;

    const uint32_t s0 = (uint32_t)__cvta_generic_to_shared(smem);
    const int nt = K >> 6;

    // ---- cp.async tile loader: A at stage base (16KB), B at +16KB ----
    const int r8 = tid >> 3;         // 0..15
    const int cc = tid & 7;          // chunk 0..7
    auto ldtile = [&](int t, int st) {
        uint32_t base = s0 + (uint32_t)st * STG_BYTES;
        int k0 = t << 6;
        #pragma unroll
        for (int p = 0; p < 8; p++) {
            int row = r8 + p * 16;
            uint32_t sc = (uint32_t)(cc ^ (row & 7));
            cpa16(base + row * 128 + sc * 16,
                  Ab + (long)(bm + row) * lda + k0 + cc * 8);
            cpa16(base + 16384u + row * 128 + sc * 16,
                  Bb + (long)(bn + row) * ldb + k0 + cc * 8);
        }
        asm volatile("cp.async.commit_group;" ::: "memory");
    };

    // ---- ldmatrix per-lane rows ----
    const int rowA  = warp_m + (lane & 15);
    const int chA   = lane >> 4;
    const int rowB  = warp_n + (lane & 7) + ((lane >> 4) << 3);
    const int chB   = (lane >> 3) & 1;

    uint32_t af[2][4][4];
    uint32_t bf[2][8][2];
    auto ldfrag = [&](int ks, int bi, uint32_t abase, uint32_t bbase) {
        int kc = ks << 1;
        #pragma unroll
        for (int i = 0; i < 4; i++) {
            int r = rowA + i * 16;
            ldsm4(af[bi][i], abase + r * 128 + (((kc + chA) ^ (r & 7)) << 4));
        }
        #pragma unroll
        for (int j4 = 0; j4 < 4; j4++) {
            int r = rowB + j4 * 16;
            uint32_t t4[4];
            ldsm4(t4, bbase + r * 128 + (((kc + chB) ^ (r & 7)) << 4));
            bf[bi][j4 * 2][0]     = t4[0];
            bf[bi][j4 * 2][1]     = t4[1];
            bf[bi][j4 * 2 + 1][0] = t4[2];
            bf[bi][j4 * 2 + 1][1] = t4[3];
        }
    };

    ldtile(0, 0);
    if (nt > 1) ldtile(1, 1);

    for (int it = 0; it < nt; it++) {
        if (it + 1 < nt) asm volatile("cp.async.wait_group 1;" ::: "memory");
        else             asm volatile("cp.async.wait_group 0;" ::: "memory");
        __syncthreads();   // orders prior-iter LDSMs before stage reuse below

        uint32_t abase = s0 + (uint32_t)(it % 3) * STG_BYTES;
        uint32_t bbase = abase + 16384u;

        ldfrag(0, 0, abase, bbase);          // first frags ASAP after barrier
        if (it + 2 < nt) ldtile(it + 2, (it + 2) % 3);

        #pragma unroll
        for (int ks = 0; ks < 4; ks++) {
            if (ks < 3) ldfrag(ks + 1, (ks + 1) & 1, abase, bbase);
            int bi = ks & 1;
            #pragma unroll
            for (int i = 0; i < 4; i++)
                #pragma unroll
                for (int j = 0; j < 8; j++)
                    mma_h(acc[i][j], af[bi][i], bf[bi][j]);
        }
    }

    // ---- epilogue ----
    if (EPI == 0) {
        float* Cb = C + (long)z * cOut;
        #pragma unroll
        for (int i = 0; i < 4; i++) {
            long r0 = bm + warp_m + i * 16 + lg;
            #pragma unroll
            for (int j = 0; j < 8; j++) {
                int col = bn + warp_n + j * 8 + lk * 2;
                *(float2*)&Cb[r0 * ldc + col] =
                    make_float2(alpha * acc[i][j][0], alpha * acc[i][j][1]);
                *(float2*)&Cb[(r0 + 8) * ldc + col] =
                    make_float2(alpha * acc[i][j][2], alpha * acc[i][j][3]);
            }
        }
    } else if (EPI == 1) {
        int sel = bn >> 11;
        int h   = (bn & 2047) >> 7;
        #pragma unroll
        for (int i = 0; i < 4; i++) {
            int rowm = bm + warp_m + i * 16 + lg;
            int b = rowm >> 11;
            int t = rowm & 2047;
            if (sel < 2) {
                float* dst = sel ? g_k : g_q;
                long base = ((long)(b * HH + h) * TT + t) * DD;
                #pragma unroll
                for (int j = 0; j < 8; j++) {
                    int d = warp_n + j * 8 + lk * 2;
                    *(float2*)&dst[base + d] =
                        make_float2(acc[i][j][0], acc[i][j][1]);
                    *(float2*)&dst[base + 8 * DD + d] =
                        make_float2(acc[i][j][2], acc[i][j][3]);
                }
            } else {
                __half* vh = (__half*)g_vh4;
                long vb = (long)(b * HH + h) * DD * TT;
                #pragma unroll
                for (int j = 0; j < 8; j++) {
                    int d = warp_n + j * 8 + lk * 2;
                    vh[vb + (long)d       * TT + t]     = __float2half_rn(acc[i][j][0]);
                    vh[vb + (long)(d + 1) * TT + t]     = __float2half_rn(acc[i][j][1]);
                    vh[vb + (long)d       * TT + t + 8] = __float2half_rn(acc[i][j][2]);
                    vh[vb + (long)(d + 1) * TT + t + 8] = __float2half_rn(acc[i][j][3]);
                }
            }
        }
    } else { // EPI == 2
        __half* yh = (__half*)g_yh4;
        int h = z % HH, b = z / HH;
        #pragma unroll
        for (int i = 0; i < 4; i++) {
            int rowm = bm + warp_m + i * 16 + lg;
            long base = ((long)(b * TT + rowm)) * CC + h * DD;
            #pragma unroll
            for (int j = 0; j < 8; j++) {
                int col = warp_n + j * 8 + lk * 2;
                *(__half2*)&yh[base + col] =
                    __floats2half2_rn(acc[i][j][0], acc[i][j][1]);
                *(__half2*)&yh[base + 8 * CC + col] =
                    __floats2half2_rn(acc[i][j][2], acc[i][j][3]);
            }
        }
    }
}

// ---------------- prepass: fp32 -> fp16 ----------------
__global__ __launch_bounds__(256)
void f2h_kernel(const float4* __restrict__ src, uint2* __restrict__ dst, int n4)
{
    int i = blockIdx.x * blockDim.x + threadIdx.x;
    if (i >= n4) return;
    float4 v = src[i];
    uint2 o;
    __half2 lo = __floats2half2_rn(v.x, v.y);
    __half2 hi = __floats2half2_rn(v.z, v.w);
    o.x = *(uint32_t*)&lo;
    o.y = *(uint32_t*)&hi;
    dst[i] = o;
}

__global__ __launch_bounds__(256)
void transpose_h_kernel(const float* __restrict__ src, __half* __restrict__ dst,
                        int R, int C)
{
    __shared__ float t[32][33];
    int c0 = blockIdx.x * 32, r0 = blockIdx.y * 32;
    int tx = threadIdx.x, ty = threadIdx.y;   // (32, 8)
    #pragma unroll
    for (int i = 0; i < 32; i += 8)
        t[ty + i][tx] = src[(long)(r0 + ty + i) * C + c0 + tx];
    __syncthreads();
    #pragma unroll
    for (int i = 0; i < 32; i += 8)
        dst[(long)(c0 + ty + i) * R + r0 + tx] = __float2half_rn(t[tx][ty + i]);
}

// ---------------- RoPE: fp32 q/k -> rotated fp16 qh/kh ----------------
__global__ __launch_bounds__(256)
void rope_kernel(const float* __restrict__ cosb, const float* __restrict__ sinb)
{
    long idx = (long)blockIdx.x * blockDim.x + threadIdx.x;
    const long total = (long)BB * HH * TT * 64;
    if (idx >= total) return;
    int d = idx & 63;
    long r = idx >> 6;
    int t = (int)(r % TT);
    long base = r * DD + d;
    float c = cosb[t * DD + d];
    float s = sinb[t * DD + d];
    __half* qh = (__half*)g_qh4;
    __half* kh = (__half*)g_kh4;
    float q0 = g_q[base], q1 = g_q[base + 64];
    qh[base]      = __float2half_rn(q0 * c - q1 * s);
    qh[base + 64] = __float2half_rn(q1 * c + q0 * s);
    float k0 = g_k[base], k1 = g_k[base + 64];
    kh[base]      = __float2half_rn(k0 * c - k1 * s);
    kh[base + 64] = __float2half_rn(k1 * c + k0 * s);
}

// ---------------- row softmax: fp32 scores -> fp16 probs ----------------
__global__ __launch_bounds__(256)
void softmax_kernel()
{
    long row = blockIdx.x;
    const float* p = g_s + row * (long)TT;
    __half* ph = (__half*)g_ph4 + row * (long)TT;
    int tid = threadIdx.x;
    float v[8];
    float mx = -1e30f;
    #pragma unroll
    for (int i = 0; i < 8; i++) {
        v[i] = p[tid + i * 256];
        mx = fmaxf(mx, v[i]);
    }
    __shared__ float sm[8];
    #pragma unroll
    for (int o = 16; o; o >>= 1) mx = fmaxf(mx, __shfl_xor_sync(0xffffffffu, mx, o));
    if ((tid & 31) == 0) sm[tid >> 5] = mx;
    __syncthreads();
    float rowmax = sm[0];
    #pragma unroll
    for (int w = 1; w < 8; w++) rowmax = fmaxf(rowmax, sm[w]);
    __syncthreads();

    float sum = 0.f;
    #pragma unroll
    for (int i = 0; i < 8; i++) {
        v[i] = expf(v[i] - rowmax);
        sum += v[i];
    }
    #pragma unroll
    for (int o = 16; o; o >>= 1) sum += __shfl_xor_sync(0xffffffffu, sum, o);
    if ((tid & 31) == 0) sm[tid >> 5] = sum;
    __syncthreads();
    float rowsum = 0.f;
    #pragma unroll
    for (int w = 0; w < 8; w++) rowsum += sm[w];
    float inv = 1.f / rowsum;
    #pragma unroll
    for (int i = 0; i < 8; i++) ph[tid + i * 256] = __float2half_rn(v[i] * inv);
}

// ---------------- launch ----------------
extern "C" void kernel_launch(void* const* d_in, const int* in_sizes, int n_in,
                              void* d_out, int out_size)
{
    const float* x     = (const float*)d_in[0];
    const float* cosb  = (const float*)d_in[1];
    const float* sinb  = (const float*)d_in[2];
    const float* Wqkv  = (const float*)d_in[3];
    const float* Wproj = (const float*)d_in[4];
    float* out = (float*)d_out;

    void *xh, *wqkvT, *wprojT, *qh, *kh, *vh, *ph, *yh;
    float *s;
    cudaGetSymbolAddress(&xh,     g_xh4);
    cudaGetSymbolAddress(&wqkvT,  g_wqkvT4);
    cudaGetSymbolAddress(&wprojT, g_wprojT4);
    cudaGetSymbolAddress(&qh, g_qh4);
    cudaGetSymbolAddress(&kh, g_kh4);
    cudaGetSymbolAddress(&vh, g_vh4);
    cudaGetSymbolAddress(&ph, g_ph4);
    cudaGetSymbolAddress(&yh, g_yh4);
    cudaGetSymbolAddress((void**)&s, g_s);

    const int SMEM = 3 * 32768;   // 96KB dynamic
    cudaFuncSetAttribute(hgemm<0>, cudaFuncAttributeMaxDynamicSharedMemorySize, SMEM);
    cudaFuncSetAttribute(hgemm<1>, cudaFuncAttributeMaxDynamicSharedMemorySize, SMEM);
    cudaFuncSetAttribute(hgemm<2>, cudaFuncAttributeMaxDynamicSharedMemorySize, SMEM);

    const float scale = 0.08838834764831845f;  // 1/sqrt(128)

    // 0) prepass: x -> half; W_qkv^T, W_proj^T -> half
    {
        int n4 = (BB * TT * CC) / 4;
        f2h_kernel<<<(n4 + 255) / 256, 256>>>((const float4*)x, (uint2*)xh, n4);
        transpose_h_kernel<<<dim3(3 * CC / 32, CC / 32), dim3(32, 8)>>>(Wqkv,  (__half*)wqkvT,  CC, 3 * CC);
        transpose_h_kernel<<<dim3(CC / 32,     CC / 32), dim3(32, 8)>>>(Wproj, (__half*)wprojT, CC, CC);
    }

    // 1) qkv = x @ W_qkv  -> q,k fp32 [B,H,T,D]; v half [B,H,D,T]
    hgemm<1><<<dim3(48, 32, 1), 128, SMEM>>>(
        (const __half*)xh, (const __half*)wqkvT, nullptr,
        2048, 2048, 2048, 0,
        0L, 0L, 0L, 1.0f);

    // 2) RoPE -> qh, kh (half)
    rope_kernel<<<16384, 256>>>(cosb, sinb);

    // 3) scores = scale * Q @ K^T -> g_s fp32 (batched over B*H)
    hgemm<0><<<dim3(16, 16, BH), 128, SMEM>>>(
        (const __half*)qh, (const __half*)kh, s,
        128, 128, 128, 2048,
        (long)TT * DD, (long)TT * DD, (long)TT * TT, scale);

    // 4) softmax -> probs half
    softmax_kernel<<<BH * TT, 256>>>();

    // 5) y = P @ V -> yh half [B*T, C]
    hgemm<2><<<dim3(1, 16, BH), 128, SMEM>>>(
        (const __half*)ph, (const __half*)vh, nullptr,
        2048, 2048, 2048, 0,
        (long)TT * TT, (long)DD * TT, 0L, 1.0f);

    // 6) out = y @ W_proj -> fp32
    hgemm<0><<<dim3(16, 32, 1), 128, SMEM>>>(
        (const __half*)yh, (const __half*)wprojT, out,
        2048, 2048, 2048, 2048,
        0L, 0L, 0L, 1.0f);
}

// round 10
// speedup vs baseline: 1.7296x; 1.2410x over previous
#include <cuda_runtime.h>
#include <cuda_fp16.h>
#include <stdint.h>
#include <math.h>

// Problem constants
#define BB 2
#define TT 2048
#define CC 2048
#define HH 16
#define DD 128
#define BH (BB*HH)          // 32
#define LOG2E 1.4426950408889634f

// ---------------- scratch (device globals, no allocation) ----------------
__device__ uint4 g_xh4   [(size_t)BB*TT*CC/8];        // x as half
__device__ uint4 g_wqkvT4[(size_t)3*CC*CC/8];         // W_qkv^T half (6144 x 2048)
__device__ uint4 g_wprojT4[(size_t)CC*CC/8];          // W_proj^T half
__device__ uint4 g_qh4   [(size_t)BB*HH*TT*DD/8];     // q half [B,H,T,D] (post-rope, pre-scaled)
__device__ uint4 g_kh4   [(size_t)BB*HH*TT*DD/8];     // k half [B,H,T,D] (post-rope)
__device__ uint4 g_vh4   [(size_t)BB*HH*DD*TT/8];     // v half [B,H,D,T] (transposed)
__device__ uint4 g_yh4   [(size_t)BB*TT*CC/8];        // y half [B*T, C]
__device__ float g_q[(size_t)BB*HH*TT*DD];            // raw fp32 q (pre-rope)
__device__ float g_k[(size_t)BB*HH*TT*DD];            // raw fp32 k (pre-rope)

// ---------------- helpers ----------------
__device__ __forceinline__ void cpa16(uint32_t dst, const void* src) {
    asm volatile("cp.async.cg.shared.global [%0], [%1], 16;" :: "r"(dst), "l"(src));
}
#define CP_COMMIT() asm volatile("cp.async.commit_group;" ::: "memory")

__device__ __forceinline__ void ldsm4(uint32_t* r, uint32_t addr) {
    asm volatile("ldmatrix.sync.aligned.m8n8.x4.shared.b16 {%0,%1,%2,%3}, [%4];"
                 : "=r"(r[0]), "=r"(r[1]), "=r"(r[2]), "=r"(r[3]) : "r"(addr));
}

__device__ __forceinline__ void mma_h(float* d, const uint32_t* a, const uint32_t* b) {
    asm volatile(
        "mma.sync.aligned.m16n8k16.row.col.f32.f16.f16.f32 "
        "{%0,%1,%2,%3}, {%4,%5,%6,%7}, {%8,%9}, {%0,%1,%2,%3};"
        : "+f"(d[0]), "+f"(d[1]), "+f"(d[2]), "+f"(d[3])
        : "r"(a[0]), "r"(a[1]), "r"(a[2]), "r"(a[3]),
          "r"(b[0]), "r"(b[1]));
}

__device__ __forceinline__ float ex2(float x) {
    float y;
    asm("ex2.approx.f32 %0, %1;" : "=f"(y) : "f"(x));
    return y;
}

// ---------------- fp16 tensor-core GEMM (from R9, unchanged core) ----------
// C = alpha * A * B^T.  CTA 128x128, K-tile 64 halves, 128 thr, 4 warps 2Mx2N,
// warp tile 64x64. 3 stages x 32KB dynamic. Reg fragment double-buffering.
// EPI 0: fp32 C + z*cOut, *alpha
// EPI 1: qkv scatter -> g_q/g_k fp32 [B,H,T,D], v half transposed [B,H,D,T]
#define STG_BYTES 32768u
template<int EPI>
__global__ __launch_bounds__(128)
void hgemm(const __half* __restrict__ A, const __half* __restrict__ B,
           float* __restrict__ C,
           int K, int lda, int ldb, int ldc,
           long batchA, long batchB, long cOut, float alpha)
{
    extern __shared__ __align__(128) char smem[];

    const int tid  = threadIdx.x;
    const int lane = tid & 31;
    const int warp = tid >> 5;
    const int warp_m = (warp & 1) * 64;
    const int warp_n = (warp >> 1) * 64;
    const int lg = lane >> 2;
    const int lk = lane & 3;

    const int z = blockIdx.z;
    const __half* Ab = A + (long)z * batchA;
    const __half* Bb = B + (long)z * batchB;
    const int bn = blockIdx.x * 128;
    const int bm = blockIdx.y * 128;

    float acc[4][8][4];
    #pragma unroll
    for (int i = 0; i < 4; i++)
        #pragma unroll
        for (int j = 0; j < 8; j++)
            #pragma unroll
            for (int c = 0; c < 4; c++) acc[i][j][c] = 0.f;

    const uint32_t s0 = (uint32_t)__cvta_generic_to_shared(smem);
    const int nt = K >> 6;

    const int r8 = tid >> 3;
    const int cc = tid & 7;
    auto ldtile = [&](int t, int st) {
        uint32_t base = s0 + (uint32_t)st * STG_BYTES;
        int k0 = t << 6;
        #pragma unroll
        for (int p = 0; p < 8; p++) {
            int row = r8 + p * 16;
            uint32_t sc = (uint32_t)(cc ^ (row & 7));
            cpa16(base + row * 128 + sc * 16,
                  Ab + (long)(bm + row) * lda + k0 + cc * 8);
            cpa16(base + 16384u + row * 128 + sc * 16,
                  Bb + (long)(bn + row) * ldb + k0 + cc * 8);
        }
        CP_COMMIT();
    };

    const int rowA  = warp_m + (lane & 15);
    const int chA   = lane >> 4;
    const int rowB  = warp_n + (lane & 7) + ((lane >> 4) << 3);
    const int chB   = (lane >> 3) & 1;

    uint32_t af[2][4][4];
    uint32_t bf[2][8][2];
    auto ldfrag = [&](int ks, int bi, uint32_t abase, uint32_t bbase) {
        int kc = ks << 1;
        #pragma unroll
        for (int i = 0; i < 4; i++) {
            int r = rowA + i * 16;
            ldsm4(af[bi][i], abase + r * 128 + (((kc + chA) ^ (r & 7)) << 4));
        }
        #pragma unroll
        for (int j4 = 0; j4 < 4; j4++) {
            int r = rowB + j4 * 16;
            uint32_t t4[4];
            ldsm4(t4, bbase + r * 128 + (((kc + chB) ^ (r & 7)) << 4));
            bf[bi][j4 * 2][0]     = t4[0];
            bf[bi][j4 * 2][1]     = t4[1];
            bf[bi][j4 * 2 + 1][0] = t4[2];
            bf[bi][j4 * 2 + 1][1] = t4[3];
        }
    };

    ldtile(0, 0);
    if (nt > 1) ldtile(1, 1);

    for (int it = 0; it < nt; it++) {
        if (it + 1 < nt) asm volatile("cp.async.wait_group 1;" ::: "memory");
        else             asm volatile("cp.async.wait_group 0;" ::: "memory");
        __syncthreads();

        uint32_t abase = s0 + (uint32_t)(it % 3) * STG_BYTES;
        uint32_t bbase = abase + 16384u;

        ldfrag(0, 0, abase, bbase);
        if (it + 2 < nt) ldtile(it + 2, (it + 2) % 3);

        #pragma unroll
        for (int ks = 0; ks < 4; ks++) {
            if (ks < 3) ldfrag(ks + 1, (ks + 1) & 1, abase, bbase);
            int bi = ks & 1;
            #pragma unroll
            for (int i = 0; i < 4; i++)
                #pragma unroll
                for (int j = 0; j < 8; j++)
                    mma_h(acc[i][j], af[bi][i], bf[bi][j]);
        }
    }

    if (EPI == 0) {
        float* Cb = C + (long)z * cOut;
        #pragma unroll
        for (int i = 0; i < 4; i++) {
            long r0 = bm + warp_m + i * 16 + lg;
            #pragma unroll
            for (int j = 0; j < 8; j++) {
                int col = bn + warp_n + j * 8 + lk * 2;
                *(float2*)&Cb[r0 * ldc + col] =
                    make_float2(alpha * acc[i][j][0], alpha * acc[i][j][1]);
                *(float2*)&Cb[(r0 + 8) * ldc + col] =
                    make_float2(alpha * acc[i][j][2], alpha * acc[i][j][3]);
            }
        }
    } else { // EPI == 1
        int sel = bn >> 11;
        int h   = (bn & 2047) >> 7;
        #pragma unroll
        for (int i = 0; i < 4; i++) {
            int rowm = bm + warp_m + i * 16 + lg;
            int b = rowm >> 11;
            int t = rowm & 2047;
            if (sel < 2) {
                float* dst = sel ? g_k : g_q;
                long base = ((long)(b * HH + h) * TT + t) * DD;
                #pragma unroll
                for (int j = 0; j < 8; j++) {
                    int d = warp_n + j * 8 + lk * 2;
                    *(float2*)&dst[base + d] =
                        make_float2(acc[i][j][0], acc[i][j][1]);
                    *(float2*)&dst[base + 8 * DD + d] =
                        make_float2(acc[i][j][2], acc[i][j][3]);
                }
            } else {
                __half* vh = (__half*)g_vh4;
                long vb = (long)(b * HH + h) * DD * TT;
                #pragma unroll
                for (int j = 0; j < 8; j++) {
                    int d = warp_n + j * 8 + lk * 2;
                    vh[vb + (long)d       * TT + t]     = __float2half_rn(acc[i][j][0]);
                    vh[vb + (long)(d + 1) * TT + t]     = __float2half_rn(acc[i][j][1]);
                    vh[vb + (long)d       * TT + t + 8] = __float2half_rn(acc[i][j][2]);
                    vh[vb + (long)(d + 1) * TT + t + 8] = __float2half_rn(acc[i][j][3]);
                }
            }
        }
    }
}

// ---------------- fused flash attention ------------------------------------
// Grid (16 q-tiles, BH). CTA: 256 thr, 8 warps x 16 q-rows. Q in regs.
// Loop 16 key-tiles of 128: S = Q K^T (mma), online softmax (regs),
// Y += P V^T (mma, V already [B,H,D,T]). K/V double-buffered cp.async.
// Smem: K st0/st1 @0/32K, V st0/st1 @64K/96K, Q @128K. Total 160KB.
// Tile format: 256 smem-rows of 128B; logical row lr = r&127, half-seg = r>>7;
// 16B chunk swizzle c ^= (r&7).
__global__ __launch_bounds__(256)
void flash_kernel(__half* __restrict__ yh_out)
{
    extern __shared__ __align__(128) char smem[];
    const uint32_t s0 = (uint32_t)__cvta_generic_to_shared(smem);
    const uint32_t QOFF = 131072u;

    const int tid  = threadIdx.x;
    const int lane = tid & 31;
    const int warp = tid >> 5;
    const int lg = lane >> 2;
    const int lk = lane & 3;

    const int bh = blockIdx.y;
    const int b = bh >> 4, h = bh & 15;
    const int qt = blockIdx.x << 7;

    const __half* qb = (const __half*)g_qh4 + (long)bh * TT * DD;
    const __half* kb = (const __half*)g_kh4 + (long)bh * TT * DD;
    const __half* vb = (const __half*)g_vh4 + (long)bh * DD * TT;

    const int r32 = tid >> 3;     // 0..31
    const int cc  = tid & 7;

    // Q tile load (rows qt..qt+127, features split into 2 segments)
    #pragma unroll
    for (int p = 0; p < 8; p++) {
        int r = r32 + p * 32;
        int lr = r & 127, seg = r >> 7;
        cpa16(s0 + QOFF + r * 128 + (((uint32_t)(cc ^ (r & 7))) << 4),
              qb + (long)(qt + lr) * DD + seg * 64 + cc * 8);
    }
    CP_COMMIT();

    auto ldKV = [&](int i, int st) {
        int t0 = i << 7;
        uint32_t kbase = s0 + (uint32_t)st * 32768u;
        uint32_t vbase = s0 + 65536u + (uint32_t)st * 32768u;
        #pragma unroll
        for (int p = 0; p < 8; p++) {
            int r = r32 + p * 32;
            int lr = r & 127, seg = r >> 7;
            uint32_t sw = (uint32_t)(r * 128 + ((cc ^ (r & 7)) << 4));
            cpa16(kbase + sw, kb + (long)(t0 + lr) * DD + seg * 64 + cc * 8);
            cpa16(vbase + sw, vb + (long)lr * TT + t0 + seg * 64 + cc * 8);
        }
        CP_COMMIT();
    };

    ldKV(0, 0);
    ldKV(1, 1);

    // Q fragments (A): 8 k16-steps x 4 regs
    asm volatile("cp.async.wait_group 2;" ::: "memory");
    __syncthreads();
    const int rowA = warp * 16 + (lane & 15);
    const int chA  = lane >> 4;
    uint32_t qf[8][4];
    #pragma unroll
    for (int ks = 0; ks < 8; ks++) {
        int r = rowA + ((ks >> 2) << 7);
        int kc = (ks & 3) * 2 + chA;
        ldsm4(qf[ks], s0 + QOFF + r * 128 + (((kc ^ (r & 7))) << 4));
    }

    const int rowB = (lane & 7) + ((lane >> 4) << 3);
    const int chB  = (lane >> 3) & 1;

    float acc_y[16][4];
    #pragma unroll
    for (int j = 0; j < 16; j++)
        #pragma unroll
        for (int c = 0; c < 4; c++) acc_y[j][c] = 0.f;
    float m0 = -1e30f, m1 = -1e30f, l0 = 0.f, l1 = 0.f;

    for (int it = 0; it < 16; it++) {
        if (it < 15) asm volatile("cp.async.wait_group 1;" ::: "memory");
        else         asm volatile("cp.async.wait_group 0;" ::: "memory");
        __syncthreads();

        uint32_t kbase = s0 + (uint32_t)(it & 1) * 32768u;
        uint32_t vbase = kbase + 65536u;

        // ---- S = Q K^T ----
        float s_[16][4];
        #pragma unroll
        for (int j = 0; j < 16; j++)
            #pragma unroll
            for (int c = 0; c < 4; c++) s_[j][c] = 0.f;
        #pragma unroll
        for (int ks = 0; ks < 8; ks++) {
            uint32_t kf[16][2];
            #pragma unroll
            for (int j8 = 0; j8 < 8; j8++) {
                int r = rowB + j8 * 16 + ((ks >> 2) << 7);
                int kc = (ks & 3) * 2 + chB;
                uint32_t t4[4];
                ldsm4(t4, kbase + r * 128 + (((kc ^ (r & 7))) << 4));
                kf[j8 * 2][0]     = t4[0];
                kf[j8 * 2][1]     = t4[1];
                kf[j8 * 2 + 1][0] = t4[2];
                kf[j8 * 2 + 1][1] = t4[3];
            }
            #pragma unroll
            for (int j = 0; j < 16; j++)
                mma_h(s_[j], qf[ks], kf[j]);
        }

        // ---- online softmax (rows: lg -> c0/c1, lg+8 -> c2/c3) ----
        float mx0 = -1e30f, mx1 = -1e30f;
        #pragma unroll
        for (int j = 0; j < 16; j++) {
            mx0 = fmaxf(mx0, fmaxf(s_[j][0], s_[j][1]));
            mx1 = fmaxf(mx1, fmaxf(s_[j][2], s_[j][3]));
        }
        mx0 = fmaxf(mx0, __shfl_xor_sync(0xffffffffu, mx0, 1));
        mx0 = fmaxf(mx0, __shfl_xor_sync(0xffffffffu, mx0, 2));
        mx1 = fmaxf(mx1, __shfl_xor_sync(0xffffffffu, mx1, 1));
        mx1 = fmaxf(mx1, __shfl_xor_sync(0xffffffffu, mx1, 2));
        float mn0 = fmaxf(m0, mx0), mn1 = fmaxf(m1, mx1);
        float corr0 = ex2((m0 - mn0) * LOG2E);
        float corr1 = ex2((m1 - mn1) * LOG2E);
        float c0f = mn0 * LOG2E, c1f = mn1 * LOG2E;
        m0 = mn0; m1 = mn1;

        float sum0 = 0.f, sum1 = 0.f;
        uint32_t pfa[16], pfb[16];
        #pragma unroll
        for (int j = 0; j < 16; j++) {
            float p0 = ex2(fmaf(s_[j][0], LOG2E, -c0f));
            float p1 = ex2(fmaf(s_[j][1], LOG2E, -c0f));
            float p2 = ex2(fmaf(s_[j][2], LOG2E, -c1f));
            float p3 = ex2(fmaf(s_[j][3], LOG2E, -c1f));
            sum0 += p0 + p1; sum1 += p2 + p3;
            __half2 ha = __floats2half2_rn(p0, p1);
            __half2 hb = __floats2half2_rn(p2, p3);
            pfa[j] = *(uint32_t*)&ha;
            pfb[j] = *(uint32_t*)&hb;
            acc_y[j][0] *= corr0; acc_y[j][1] *= corr0;
            acc_y[j][2] *= corr1; acc_y[j][3] *= corr1;
        }
        sum0 += __shfl_xor_sync(0xffffffffu, sum0, 1);
        sum0 += __shfl_xor_sync(0xffffffffu, sum0, 2);
        sum1 += __shfl_xor_sync(0xffffffffu, sum1, 1);
        sum1 += __shfl_xor_sync(0xffffffffu, sum1, 2);
        l0 = l0 * corr0 + sum0;
        l1 = l1 * corr1 + sum1;

        // ---- Y += P V^T ----
        #pragma unroll
        for (int ks = 0; ks < 8; ks++) {
            uint32_t vf[16][2];
            #pragma unroll
            for (int j8 = 0; j8 < 8; j8++) {
                int r = rowB + j8 * 16 + ((ks >> 2) << 7);
                int kc = (ks & 3) * 2 + chB;
                uint32_t t4[4];
                ldsm4(t4, vbase + r * 128 + (((kc ^ (r & 7))) << 4));
                vf[j8 * 2][0]     = t4[0];
                vf[j8 * 2][1]     = t4[1];
                vf[j8 * 2 + 1][0] = t4[2];
                vf[j8 * 2 + 1][1] = t4[3];
            }
            uint32_t pa[4] = { pfa[2 * ks], pfb[2 * ks], pfa[2 * ks + 1], pfb[2 * ks + 1] };
            #pragma unroll
            for (int j = 0; j < 16; j++)
                mma_h(acc_y[j], pa, vf[j]);
        }

        __syncthreads();                       // all warps done with stage it&1
        if (it + 2 < 16) ldKV(it + 2, it & 1); // reuse freed stage
    }

    // ---- epilogue: normalize and store ----
    float inv0 = 1.f / l0, inv1 = 1.f / l1;
    int row0 = qt + warp * 16 + lg;
    long base0 = ((long)(b * TT + row0)) * CC + h * DD;
    long base1 = base0 + 8L * CC;
    #pragma unroll
    for (int j = 0; j < 16; j++) {
        int col = j * 8 + lk * 2;
        __half2 o0 = __floats2half2_rn(acc_y[j][0] * inv0, acc_y[j][1] * inv0);
        __half2 o1 = __floats2half2_rn(acc_y[j][2] * inv1, acc_y[j][3] * inv1);
        *(__half2*)&yh_out[base0 + col] = o0;
        *(__half2*)&yh_out[base1 + col] = o1;
    }
}

// ---------------- prepass: fp32 -> fp16 ----------------
__global__ __launch_bounds__(256)
void f2h_kernel(const float4* __restrict__ src, uint2* __restrict__ dst, int n4)
{
    int i = blockIdx.x * blockDim.x + threadIdx.x;
    if (i >= n4) return;
    float4 v = src[i];
    uint2 o;
    __half2 lo = __floats2half2_rn(v.x, v.y);
    __half2 hi = __floats2half2_rn(v.z, v.w);
    o.x = *(uint32_t*)&lo;
    o.y = *(uint32_t*)&hi;
    dst[i] = o;
}

__global__ __launch_bounds__(256)
void transpose_h_kernel(const float* __restrict__ src, __half* __restrict__ dst,
                        int R, int C)
{
    __shared__ float t[32][33];
    int c0 = blockIdx.x * 32, r0 = blockIdx.y * 32;
    int tx = threadIdx.x, ty = threadIdx.y;   // (32, 8)
    #pragma unroll
    for (int i = 0; i < 32; i += 8)
        t[ty + i][tx] = src[(long)(r0 + ty + i) * C + c0 + tx];
    __syncthreads();
    #pragma unroll
    for (int i = 0; i < 32; i += 8)
        dst[(long)(c0 + ty + i) * R + r0 + tx] = __float2half_rn(t[tx][ty + i]);
}

// ---------------- RoPE: fp32 q/k -> rotated fp16; q pre-scaled by 1/sqrt(D) --
__global__ __launch_bounds__(256)
void rope_kernel(const float* __restrict__ cosb, const float* __restrict__ sinb)
{
    const float scale = 0.08838834764831845f;
    long idx = (long)blockIdx.x * blockDim.x + threadIdx.x;
    const long total = (long)BB * HH * TT * 64;
    if (idx >= total) return;
    int d = idx & 63;
    long r = idx >> 6;
    int t = (int)(r % TT);
    long base = r * DD + d;
    float c = cosb[t * DD + d];
    float s = sinb[t * DD + d];
    __half* qh = (__half*)g_qh4;
    __half* kh = (__half*)g_kh4;
    float q0 = g_q[base], q1 = g_q[base + 64];
    qh[base]      = __float2half_rn((q0 * c - q1 * s) * scale);
    qh[base + 64] = __float2half_rn((q1 * c + q0 * s) * scale);
    float k0 = g_k[base], k1 = g_k[base + 64];
    kh[base]      = __float2half_rn(k0 * c - k1 * s);
    kh[base + 64] = __float2half_rn(k1 * c + k0 * s);
}

// ---------------- launch ----------------
extern "C" void kernel_launch(void* const* d_in, const int* in_sizes, int n_in,
                              void* d_out, int out_size)
{
    const float* x     = (const float*)d_in[0];
    const float* cosb  = (const float*)d_in[1];
    const float* sinb  = (const float*)d_in[2];
    const float* Wqkv  = (const float*)d_in[3];
    const float* Wproj = (const float*)d_in[4];
    float* out = (float*)d_out;

    void *xh, *wqkvT, *wprojT, *yh;
    cudaGetSymbolAddress(&xh,     g_xh4);
    cudaGetSymbolAddress(&wqkvT,  g_wqkvT4);
    cudaGetSymbolAddress(&wprojT, g_wprojT4);
    cudaGetSymbolAddress(&yh, g_yh4);

    const int SMEM  = 3 * 32768;     // 96KB dynamic (hgemm)
    const int FSMEM = 5 * 32768;     // 160KB dynamic (flash)
    cudaFuncSetAttribute(hgemm<0>, cudaFuncAttributeMaxDynamicSharedMemorySize, SMEM);
    cudaFuncSetAttribute(hgemm<1>, cudaFuncAttributeMaxDynamicSharedMemorySize, SMEM);
    cudaFuncSetAttribute(flash_kernel, cudaFuncAttributeMaxDynamicSharedMemorySize, FSMEM);

    // 0) prepass: x -> half; W_qkv^T, W_proj^T -> half
    {
        int n4 = (BB * TT * CC) / 4;
        f2h_kernel<<<(n4 + 255) / 256, 256>>>((const float4*)x, (uint2*)xh, n4);
        transpose_h_kernel<<<dim3(3 * CC / 32, CC / 32), dim3(32, 8)>>>(Wqkv,  (__half*)wqkvT,  CC, 3 * CC);
        transpose_h_kernel<<<dim3(CC / 32,     CC / 32), dim3(32, 8)>>>(Wproj, (__half*)wprojT, CC, CC);
    }

    // 1) qkv = x @ W_qkv  -> q,k fp32 [B,H,T,D]; v half [B,H,D,T]
    hgemm<1><<<dim3(48, 32, 1), 128, SMEM>>>(
        (const __half*)xh, (const __half*)wqkvT, nullptr,
        2048, 2048, 2048, 0,
        0L, 0L, 0L, 1.0f);

    // 2) RoPE -> qh (pre-scaled), kh
    rope_kernel<<<16384, 256>>>(cosb, sinb);

    // 3) fused attention: softmax(Q K^T) V -> yh half [B*T, C]
    flash_kernel<<<dim3(16, BH), 256, FSMEM>>>((__half*)yh);

    // 4) out = y @ W_proj -> fp32
    hgemm<0><<<dim3(16, 32, 1), 128, SMEM>>>(
        (const __half*)yh, (const __half*)wprojT, out,
        2048, 2048, 2048, 2048,
        0L, 0L, 0L, 1.0f);
}